// round 10
// baseline (speedup 1.0000x reference)
#include <cuda_runtime.h>
#include <cuda_fp16.h>
#include <cstdint>

#define DDIM 128
#define NMAX 100000
#define EMAX 1000000
#define EPS 1e-5f
#define SLOTS 64

// ---------------- scratch (device globals; no runtime allocation) ----------
__device__ __align__(256) __half g_agg16[(size_t)NMAX * DDIM];  // A, then h(fp16)
__device__ __align__(256) __half g_feat16[(size_t)NMAX * DDIM];
__device__ __align__(256) int g_cnt[NMAX];
__device__ __align__(256) int g_ell[(size_t)NMAX * SLOTS];
__device__ __align__(16) float g_colsum[DDIM];
__device__ __align__(16) float g_colsumsq[DDIM];

// ---------------- K0: zero counters/stats + feature -> fp16 ----------------
__global__ void __launch_bounds__(256) k_init(const float* __restrict__ feat,
                                              int N, int nf4) {
    int stride = gridDim.x * blockDim.x;
    int tid0 = blockIdx.x * blockDim.x + threadIdx.x;
    for (int j = tid0; j < N; j += stride) g_cnt[j] = 0;
    if (tid0 < DDIM) { g_colsum[tid0] = 0.f; g_colsumsq[tid0] = 0.f; }
    for (int i = tid0; i < nf4; i += stride) {
        float4 v = reinterpret_cast<const float4*>(feat)[i];
        __half2 h0 = __floats2half2_rn(v.x, v.y);
        __half2 h1 = __floats2half2_rn(v.z, v.w);
        uint2 u;
        u.x = *reinterpret_cast<uint32_t*>(&h0);
        u.y = *reinterpret_cast<uint32_t*>(&h1);
        reinterpret_cast<uint2*>(g_feat16)[i] = u;
    }
}

// ---------------- K1: ELL insert ----------------
__global__ void k_insert(const int* __restrict__ src,
                         const int* __restrict__ dst, int E) {
    int i = blockIdx.x * blockDim.x + threadIdx.x;
    if (i >= E) return;
    int d = dst[i];
    int pos = atomicAdd(&g_cnt[d], 1);
    if (pos < SLOTS) g_ell[d * SLOTS + pos] = src[i];
}

// ---------------- K2: gather-mean per node (1 warp / node), fp16 in/out ----
__global__ void __launch_bounds__(256) k_gather(int N) {
    uint32_t node = (blockIdx.x * blockDim.x + threadIdx.x) >> 5;
    uint32_t lane = threadIdx.x & 31;
    if (node >= (uint32_t)N) return;
    int cnt = g_cnt[node];
    int m = cnt < SLOTS ? cnt : SLOTS;
    const int* slots = g_ell + node * SLOTS;
    const uint2* f2p = reinterpret_cast<const uint2*>(g_feat16);
    float4 acc = make_float4(0.f, 0.f, 0.f, 0.f);
    int e = 0;
    for (; e + 4 <= m; e += 4) {
        uint32_t s0 = (uint32_t)slots[e] * 32u + lane;
        uint32_t s1 = (uint32_t)slots[e + 1] * 32u + lane;
        uint32_t s2 = (uint32_t)slots[e + 2] * 32u + lane;
        uint32_t s3 = (uint32_t)slots[e + 3] * 32u + lane;
        uint2 u0 = f2p[s0];
        uint2 u1 = f2p[s1];
        uint2 u2 = f2p[s2];
        uint2 u3 = f2p[s3];
        __half2 p0 = __hadd2(*reinterpret_cast<__half2*>(&u0.x),
                             *reinterpret_cast<__half2*>(&u1.x));
        __half2 p1 = __hadd2(*reinterpret_cast<__half2*>(&u0.y),
                             *reinterpret_cast<__half2*>(&u1.y));
        __half2 q0 = __hadd2(*reinterpret_cast<__half2*>(&u2.x),
                             *reinterpret_cast<__half2*>(&u3.x));
        __half2 q1 = __hadd2(*reinterpret_cast<__half2*>(&u2.y),
                             *reinterpret_cast<__half2*>(&u3.y));
        float2 f0 = __half22float2(p0);
        float2 f1 = __half22float2(p1);
        float2 e0 = __half22float2(q0);
        float2 e1 = __half22float2(q1);
        acc.x += f0.x + e0.x;
        acc.y += f0.y + e0.y;
        acc.z += f1.x + e1.x;
        acc.w += f1.y + e1.y;
    }
    if (e + 2 <= m) {
        uint32_t s0 = (uint32_t)slots[e] * 32u + lane;
        uint32_t s1 = (uint32_t)slots[e + 1] * 32u + lane;
        uint2 u0 = f2p[s0];
        uint2 u1 = f2p[s1];
        __half2 p0 = __hadd2(*reinterpret_cast<__half2*>(&u0.x),
                             *reinterpret_cast<__half2*>(&u1.x));
        __half2 p1 = __hadd2(*reinterpret_cast<__half2*>(&u0.y),
                             *reinterpret_cast<__half2*>(&u1.y));
        float2 f0 = __half22float2(p0);
        float2 f1 = __half22float2(p1);
        acc.x += f0.x; acc.y += f0.y; acc.z += f1.x; acc.w += f1.y;
        e += 2;
    }
    if (e < m) {
        uint32_t s0 = (uint32_t)slots[e] * 32u + lane;
        uint2 u0 = f2p[s0];
        float2 f0 = __half22float2(*reinterpret_cast<__half2*>(&u0.x));
        float2 f1 = __half22float2(*reinterpret_cast<__half2*>(&u0.y));
        acc.x += f0.x; acc.y += f0.y; acc.z += f1.x; acc.w += f1.y;
    }
    float inv = 1.0f / fmaxf((float)cnt, 1.0f);
    __half2 o0 = __floats2half2_rn(acc.x * inv, acc.y * inv);
    __half2 o1 = __floats2half2_rn(acc.z * inv, acc.w * inv);
    uint2 ov;
    ov.x = *reinterpret_cast<uint32_t*>(&o0);
    ov.y = *reinterpret_cast<uint32_t*>(&o1);
    reinterpret_cast<uint2*>(g_agg16)[node * 32u + lane] = ov;
}

// ---------------- K3: fp16 mma GEMM, B via ldmatrix.x4, h out fp16 ---------
#define LDPH 136
#define LDPF 132
__global__ void __launch_bounds__(256, 2)
k_gemm_mma(const float* __restrict__ W, const float* __restrict__ b, int N) {
    extern __shared__ __half sW[];       // [128][136] halves = 34816 B
    float* sH = reinterpret_cast<float*>(sW);  // epilogue reuse
    __shared__ float sBias[DDIM];

    int tid = threadIdx.x;
    int wid = tid >> 5;
    int lane = tid & 31;
    int g = lane >> 2;
    int tig = lane & 3;
    int row0 = blockIdx.x * 128;

    if (tid < DDIM) sBias[tid] = b[tid];

    // stage W [n][k] fp32 -> fp16
    const float4* w4 = reinterpret_cast<const float4*>(W);
    #pragma unroll
    for (int it = 0; it < 16; it++) {
        int idx = it * 256 + tid;
        int r = idx >> 5;
        int kc = idx & 31;
        float4 v = w4[r * 32 + kc];
        __half2 h0 = __floats2half2_rn(v.x, v.y);
        __half2 h1 = __floats2half2_rn(v.z, v.w);
        uint2 u;
        u.x = *reinterpret_cast<uint32_t*>(&h0);
        u.y = *reinterpret_cast<uint32_t*>(&h1);
        *reinterpret_cast<uint2*>(&sW[r * LDPH + kc * 4]) = u;
    }
    __syncthreads();

    int wr = wid * 16;
    int gr0 = row0 + wr + g;
    int gr1 = gr0 + 8;
    bool v0 = gr0 < N, v1 = gr1 < N;
    const __half* p0 = g_agg16 + (size_t)(v0 ? gr0 : 0) * DDIM;
    const __half* p1 = g_agg16 + (size_t)(v1 ? gr1 : 0) * DDIM;

    float acc[16][4];
    #pragma unroll
    for (int nt = 0; nt < 16; nt++)
        #pragma unroll
        for (int c = 0; c < 4; c++) acc[nt][c] = 0.f;

    // ldmatrix lane-invariant address part:
    // matrix j = lane>>3: j>>1 selects nt within pair, j&1 selects k-half
    uint32_t sW_u32;
    {
        uint64_t t64 = __cvta_generic_to_shared(sW);
        sW_u32 = (uint32_t)t64;
    }
    uint32_t lrow = ((lane >> 4) & 1) * 8 + (lane & 7);   // row within 16-row pair
    uint32_t khalf = ((lane >> 3) & 1) * 8;               // 0 or 8 halves
    uint32_t laneoff = sW_u32 + 2u * (lrow * LDPH + khalf);

    uint32_t a0 = *reinterpret_cast<const uint32_t*>(p0 + 2 * tig);
    uint32_t a2 = *reinterpret_cast<const uint32_t*>(p0 + 2 * tig + 8);
    uint32_t a1 = *reinterpret_cast<const uint32_t*>(p1 + 2 * tig);
    uint32_t a3 = *reinterpret_cast<const uint32_t*>(p1 + 2 * tig + 8);

    #pragma unroll
    for (int ks = 0; ks < 8; ks++) {
        int k0 = ks * 16;
        uint32_t ua0 = a0, ua1 = a1, ua2 = a2, ua3 = a3;
        if (ks < 7) {
            int kn = k0 + 16 + 2 * tig;
            a0 = *reinterpret_cast<const uint32_t*>(p0 + kn);
            a2 = *reinterpret_cast<const uint32_t*>(p0 + kn + 8);
            a1 = *reinterpret_cast<const uint32_t*>(p1 + kn);
            a3 = *reinterpret_cast<const uint32_t*>(p1 + kn + 8);
        }
        #pragma unroll
        for (int ntp = 0; ntp < 8; ntp++) {
            uint32_t addr = laneoff + 2u * (ntp * 16 * LDPH + k0);
            uint32_t b0r, b1r, b2r, b3r;
            asm volatile(
                "ldmatrix.sync.aligned.m8n8.x4.shared.b16 {%0,%1,%2,%3}, [%4];"
                : "=r"(b0r), "=r"(b1r), "=r"(b2r), "=r"(b3r) : "r"(addr));
            int nt0 = ntp * 2;
            asm volatile(
                "mma.sync.aligned.m16n8k16.row.col.f32.f16.f16.f32 "
                "{%0,%1,%2,%3}, {%4,%5,%6,%7}, {%8,%9}, {%0,%1,%2,%3};"
                : "+f"(acc[nt0][0]), "+f"(acc[nt0][1]),
                  "+f"(acc[nt0][2]), "+f"(acc[nt0][3])
                : "r"(ua0), "r"(ua1), "r"(ua2), "r"(ua3),
                  "r"(b0r), "r"(b1r));
            asm volatile(
                "mma.sync.aligned.m16n8k16.row.col.f32.f16.f16.f32 "
                "{%0,%1,%2,%3}, {%4,%5,%6,%7}, {%8,%9}, {%0,%1,%2,%3};"
                : "+f"(acc[nt0 + 1][0]), "+f"(acc[nt0 + 1][1]),
                  "+f"(acc[nt0 + 1][2]), "+f"(acc[nt0 + 1][3])
                : "r"(ua0), "r"(ua1), "r"(ua2), "r"(ua3),
                  "r"(b2r), "r"(b3r));
        }
    }
    __syncthreads();   // done with sW; reuse as fp32 h staging (64 rows/window)

    #pragma unroll
    for (int half = 0; half < 2; half++) {
        if ((wid >> 2) == half) {
            int lr = (wid & 3) * 16;
            #pragma unroll
            for (int nt = 0; nt < 16; nt++) {
                int c = nt * 8 + 2 * tig;
                float b0 = sBias[c], b1 = sBias[c + 1];
                float2 q0 = make_float2(acc[nt][0] + b0, acc[nt][1] + b1);
                float2 q1 = make_float2(acc[nt][2] + b0, acc[nt][3] + b1);
                *reinterpret_cast<float2*>(&sH[(lr + g) * LDPF + c]) = q0;
                *reinterpret_cast<float2*>(&sH[(lr + g + 8) * LDPF + c]) = q1;
            }
        }
        __syncthreads();
        int base = half * 64;
        int valid = N - row0 - base;
        if (valid > 64) valid = 64;
        {
            int col = tid & 127;
            int rbeg = (tid >> 7) * 32;
            int rend = rbeg + 32;
            if (rend > valid) rend = valid;
            float s = 0.f, s2 = 0.f;
            for (int r = rbeg; r < rend; r++) {
                float v = sH[r * LDPF + col];
                s += v;
                s2 += v * v;
            }
            if (rbeg < valid) {
                atomicAdd(&g_colsum[col], s);
                atomicAdd(&g_colsumsq[col], s2);
            }
        }
        // store h window as fp16 into g_agg16 (rows already consumed as A)
        #pragma unroll
        for (int it = 0; it < 8; it++) {
            int idx = it * 256 + tid;
            int r = idx >> 5;
            int kc = idx & 31;
            int gr = row0 + base + r;
            if (gr < N) {
                float4 v = *reinterpret_cast<float4*>(&sH[r * LDPF + kc * 4]);
                __half2 h0 = __floats2half2_rn(v.x, v.y);
                __half2 h1 = __floats2half2_rn(v.z, v.w);
                uint2 u;
                u.x = *reinterpret_cast<uint32_t*>(&h0);
                u.y = *reinterpret_cast<uint32_t*>(&h1);
                reinterpret_cast<uint2*>(g_agg16)[(size_t)gr * 32 + kc] = u;
            }
        }
        if (half == 0) __syncthreads();
    }
}

// ---------------- K4: finalize: out = feat + relu(h16*scale + shift) -------
__global__ void __launch_bounds__(256)
k_final(const float* __restrict__ feat, const float* __restrict__ gamma,
        const float* __restrict__ beta, float* __restrict__ out,
        float invN, int nf4) {
    __shared__ float sScale[DDIM];
    __shared__ float sShift[DDIM];
    int tid = threadIdx.x;
    if (tid < DDIM) {
        float mean = g_colsum[tid] * invN;
        float var = g_colsumsq[tid] * invN - mean * mean;
        float rstd = rsqrtf(var + EPS);
        float sc = rstd * gamma[tid];
        sScale[tid] = sc;
        sShift[tid] = beta[tid] - mean * sc;
    }
    __syncthreads();
    int stride = gridDim.x * blockDim.x;
    const uint2* h2 = reinterpret_cast<const uint2*>(g_agg16);
    for (int i = blockIdx.x * blockDim.x + tid; i < nf4; i += stride) {
        int c = (i & 31) << 2;
        uint2 hu = h2[i];
        float2 h0 = __half22float2(*reinterpret_cast<__half2*>(&hu.x));
        float2 h1 = __half22float2(*reinterpret_cast<__half2*>(&hu.y));
        float4 fv = reinterpret_cast<const float4*>(feat)[i];
        float4 o;
        o.x = fmaxf(h0.x * sScale[c + 0] + sShift[c + 0], 0.f) + fv.x;
        o.y = fmaxf(h0.y * sScale[c + 1] + sShift[c + 1], 0.f) + fv.y;
        o.z = fmaxf(h1.x * sScale[c + 2] + sShift[c + 2], 0.f) + fv.z;
        o.w = fmaxf(h1.y * sScale[c + 3] + sShift[c + 3], 0.f) + fv.w;
        reinterpret_cast<float4*>(out)[i] = o;
    }
}

// ---------------- launch ----------------
extern "C" void kernel_launch(void* const* d_in, const int* in_sizes, int n_in,
                              void* d_out, int out_size) {
    const float* feature = (const float*)d_in[0];
    const int*   src     = (const int*)d_in[1];
    const int*   dst     = (const int*)d_in[2];
    const float* W       = (const float*)d_in[3];
    const float* b       = (const float*)d_in[4];
    const float* gamma   = (const float*)d_in[5];
    const float* beta    = (const float*)d_in[6];
    float* out = (float*)d_out;

    int N = in_sizes[0] / DDIM;   // 100000
    int E = in_sizes[1];          // 1000000
    int nf4 = N * (DDIM / 4);

    k_init<<<592, 256>>>(feature, N, nf4);
    k_insert<<<(E + 255) / 256, 256>>>(src, dst, E);

    int gw_blocks = ((N * 32) + 255) / 256;
    k_gather<<<gw_blocks, 256>>>(N);

    size_t smem = (size_t)(128 * LDPH) * sizeof(__half);   // 34816 B
    size_t smemf = (size_t)(64 * LDPF) * sizeof(float);    // 33792 B
    if (smemf > smem) smem = smemf;
    cudaFuncSetAttribute(k_gemm_mma,
                         cudaFuncAttributeMaxDynamicSharedMemorySize,
                         (int)smem);
    int gblocks = (N + 127) / 128;
    k_gemm_mma<<<gblocks, 256, smem>>>(W, b, N);

    k_final<<<1184, 256>>>(feature, gamma, beta, out, 1.0f / (float)N, nf4);
}

// round 11
// speedup vs baseline: 1.0439x; 1.0439x over previous
#include <cuda_runtime.h>
#include <cuda_fp16.h>
#include <cstdint>

#define DDIM 128
#define NMAX 100000
#define EMAX 1000000
#define EPS 1e-5f
#define SLOTS 64

// ---------------- scratch (device globals; no runtime allocation) ----------
__device__ __align__(256) __half g_agg16[(size_t)NMAX * DDIM];
__device__ __align__(256) __half g_feat16[(size_t)NMAX * DDIM];
__device__ __align__(256) int g_cnt[NMAX];
__device__ __align__(256) int g_ell[(size_t)NMAX * SLOTS];
__device__ __align__(16) float g_colsum[DDIM];
__device__ __align__(16) float g_colsumsq[DDIM];

// ---------------- K0: zero counters/stats + feature -> fp16 ----------------
__global__ void __launch_bounds__(256) k_init(const float* __restrict__ feat,
                                              int N, int nf4) {
    int stride = gridDim.x * blockDim.x;
    int tid0 = blockIdx.x * blockDim.x + threadIdx.x;
    for (int j = tid0; j < N; j += stride) g_cnt[j] = 0;
    if (tid0 < DDIM) { g_colsum[tid0] = 0.f; g_colsumsq[tid0] = 0.f; }
    for (int i = tid0; i < nf4; i += stride) {
        float4 v = reinterpret_cast<const float4*>(feat)[i];
        __half2 h0 = __floats2half2_rn(v.x, v.y);
        __half2 h1 = __floats2half2_rn(v.z, v.w);
        uint2 u;
        u.x = *reinterpret_cast<uint32_t*>(&h0);
        u.y = *reinterpret_cast<uint32_t*>(&h1);
        reinterpret_cast<uint2*>(g_feat16)[i] = u;
    }
}

// ---------------- K1: ELL insert ----------------
__global__ void k_insert(const int* __restrict__ src,
                         const int* __restrict__ dst, int E) {
    int i = blockIdx.x * blockDim.x + threadIdx.x;
    if (i >= E) return;
    int d = dst[i];
    int pos = atomicAdd(&g_cnt[d], 1);
    if (pos < SLOTS) g_ell[d * SLOTS + pos] = src[i];
}

// ---------------- K2: gather-mean per node (1 warp / node), fp16 in/out ----
__global__ void __launch_bounds__(256) k_gather(int N) {
    uint32_t node = (blockIdx.x * blockDim.x + threadIdx.x) >> 5;
    uint32_t lane = threadIdx.x & 31;
    if (node >= (uint32_t)N) return;
    int cnt = g_cnt[node];
    int m = cnt < SLOTS ? cnt : SLOTS;
    const int* slots = g_ell + node * SLOTS;
    const uint2* f2p = reinterpret_cast<const uint2*>(g_feat16);
    float4 acc = make_float4(0.f, 0.f, 0.f, 0.f);
    int e = 0;
    for (; e + 4 <= m; e += 4) {
        uint32_t s0 = (uint32_t)slots[e] * 32u + lane;
        uint32_t s1 = (uint32_t)slots[e + 1] * 32u + lane;
        uint32_t s2 = (uint32_t)slots[e + 2] * 32u + lane;
        uint32_t s3 = (uint32_t)slots[e + 3] * 32u + lane;
        uint2 u0 = f2p[s0];
        uint2 u1 = f2p[s1];
        uint2 u2 = f2p[s2];
        uint2 u3 = f2p[s3];
        __half2 p0 = __hadd2(*reinterpret_cast<__half2*>(&u0.x),
                             *reinterpret_cast<__half2*>(&u1.x));
        __half2 p1 = __hadd2(*reinterpret_cast<__half2*>(&u0.y),
                             *reinterpret_cast<__half2*>(&u1.y));
        __half2 q0 = __hadd2(*reinterpret_cast<__half2*>(&u2.x),
                             *reinterpret_cast<__half2*>(&u3.x));
        __half2 q1 = __hadd2(*reinterpret_cast<__half2*>(&u2.y),
                             *reinterpret_cast<__half2*>(&u3.y));
        float2 f0 = __half22float2(p0);
        float2 f1 = __half22float2(p1);
        float2 e0 = __half22float2(q0);
        float2 e1 = __half22float2(q1);
        acc.x += f0.x + e0.x;
        acc.y += f0.y + e0.y;
        acc.z += f1.x + e1.x;
        acc.w += f1.y + e1.y;
    }
    if (e + 2 <= m) {
        uint32_t s0 = (uint32_t)slots[e] * 32u + lane;
        uint32_t s1 = (uint32_t)slots[e + 1] * 32u + lane;
        uint2 u0 = f2p[s0];
        uint2 u1 = f2p[s1];
        __half2 p0 = __hadd2(*reinterpret_cast<__half2*>(&u0.x),
                             *reinterpret_cast<__half2*>(&u1.x));
        __half2 p1 = __hadd2(*reinterpret_cast<__half2*>(&u0.y),
                             *reinterpret_cast<__half2*>(&u1.y));
        float2 f0 = __half22float2(p0);
        float2 f1 = __half22float2(p1);
        acc.x += f0.x; acc.y += f0.y; acc.z += f1.x; acc.w += f1.y;
        e += 2;
    }
    if (e < m) {
        uint32_t s0 = (uint32_t)slots[e] * 32u + lane;
        uint2 u0 = f2p[s0];
        float2 f0 = __half22float2(*reinterpret_cast<__half2*>(&u0.x));
        float2 f1 = __half22float2(*reinterpret_cast<__half2*>(&u0.y));
        acc.x += f0.x; acc.y += f0.y; acc.z += f1.x; acc.w += f1.y;
    }
    float inv = 1.0f / fmaxf((float)cnt, 1.0f);
    __half2 o0 = __floats2half2_rn(acc.x * inv, acc.y * inv);
    __half2 o1 = __floats2half2_rn(acc.z * inv, acc.w * inv);
    uint2 ov;
    ov.x = *reinterpret_cast<uint32_t*>(&o0);
    ov.y = *reinterpret_cast<uint32_t*>(&o1);
    reinterpret_cast<uint2*>(g_agg16)[node * 32u + lane] = ov;
}

// ---------------- K3: fp16 mma GEMM, A+B staged in smem, ldmatrix loads ----
#define LDPH 136
#define LDPF 132
__global__ void __launch_bounds__(256, 2)
k_gemm_mma(const float* __restrict__ W, const float* __restrict__ b,
           float* __restrict__ h, int N) {
    extern __shared__ __half smemh[];
    __half* sW = smemh;                  // [128][136] = 34816 B
    __half* sA = smemh + 128 * LDPH;     // [128][136] = 34816 B
    float* sH = reinterpret_cast<float*>(smemh);   // epilogue reuse
    __shared__ float sBias[DDIM];

    int tid = threadIdx.x;
    int wid = tid >> 5;
    int lane = tid & 31;
    int g = lane >> 2;
    int tig = lane & 3;
    int row0 = blockIdx.x * 128;

    if (tid < DDIM) sBias[tid] = b[tid];

    // stage A (coalesced uint4 loads from g_agg16; 8 per thread)
    {
        const uint4* a4 = reinterpret_cast<const uint4*>(g_agg16);
        #pragma unroll
        for (int it = 0; it < 8; it++) {
            int idx = it * 256 + tid;          // uint4 idx in [0,2048)
            int r = idx >> 4;                  // 16 uint4 per row
            int c = idx & 15;                  // uint4 within row (8 halves)
            int gr = row0 + r;
            uint4 v = (gr < N) ? a4[(size_t)gr * 16 + c]
                               : make_uint4(0u, 0u, 0u, 0u);
            *reinterpret_cast<uint4*>(&sA[r * LDPH + c * 8]) = v;
        }
    }
    // stage W [n][k] fp32 -> fp16
    const float4* w4 = reinterpret_cast<const float4*>(W);
    #pragma unroll
    for (int it = 0; it < 16; it++) {
        int idx = it * 256 + tid;
        int r = idx >> 5;
        int kc = idx & 31;
        float4 v = w4[r * 32 + kc];
        __half2 h0 = __floats2half2_rn(v.x, v.y);
        __half2 h1 = __floats2half2_rn(v.z, v.w);
        uint2 u;
        u.x = *reinterpret_cast<uint32_t*>(&h0);
        u.y = *reinterpret_cast<uint32_t*>(&h1);
        *reinterpret_cast<uint2*>(&sW[r * LDPH + kc * 4]) = u;
    }
    __syncthreads();

    int wr = wid * 16;
    float acc[16][4];
    #pragma unroll
    for (int nt = 0; nt < 16; nt++)
        #pragma unroll
        for (int c = 0; c < 4; c++) acc[nt][c] = 0.f;

    uint32_t sW_u32 = (uint32_t)__cvta_generic_to_shared(sW);
    uint32_t sA_u32 = (uint32_t)__cvta_generic_to_shared(sA);
    // B ldmatrix lane mapping (matrix pairs over nt, k-halves)
    uint32_t b_lrow = ((lane >> 4) & 1) * 8 + (lane & 7);
    uint32_t b_khalf = ((lane >> 3) & 1) * 8;
    uint32_t b_laneoff = sW_u32 + 2u * (b_lrow * LDPH + b_khalf);
    // A ldmatrix lane mapping: {a0,a1,a2,a3} = (rows,k0),(rows+8,k0),(rows,k0+8),(rows+8,k0+8)
    uint32_t a_row = (uint32_t)wr + ((lane >> 3) & 1) * 8 + (lane & 7);
    uint32_t a_khalf = (lane >> 4) * 8;
    uint32_t a_laneoff = sA_u32 + 2u * (a_row * LDPH + a_khalf);

    #pragma unroll
    for (int ks = 0; ks < 8; ks++) {
        int k0 = ks * 16;
        uint32_t ua0, ua1, ua2, ua3;
        asm volatile(
            "ldmatrix.sync.aligned.m8n8.x4.shared.b16 {%0,%1,%2,%3}, [%4];"
            : "=r"(ua0), "=r"(ua1), "=r"(ua2), "=r"(ua3)
            : "r"(a_laneoff + 2u * (uint32_t)k0));
        #pragma unroll
        for (int ntp = 0; ntp < 8; ntp++) {
            uint32_t addr = b_laneoff + 2u * (ntp * 16 * LDPH + k0);
            uint32_t b0r, b1r, b2r, b3r;
            asm volatile(
                "ldmatrix.sync.aligned.m8n8.x4.shared.b16 {%0,%1,%2,%3}, [%4];"
                : "=r"(b0r), "=r"(b1r), "=r"(b2r), "=r"(b3r) : "r"(addr));
            int nt0 = ntp * 2;
            asm volatile(
                "mma.sync.aligned.m16n8k16.row.col.f32.f16.f16.f32 "
                "{%0,%1,%2,%3}, {%4,%5,%6,%7}, {%8,%9}, {%0,%1,%2,%3};"
                : "+f"(acc[nt0][0]), "+f"(acc[nt0][1]),
                  "+f"(acc[nt0][2]), "+f"(acc[nt0][3])
                : "r"(ua0), "r"(ua1), "r"(ua2), "r"(ua3),
                  "r"(b0r), "r"(b1r));
            asm volatile(
                "mma.sync.aligned.m16n8k16.row.col.f32.f16.f16.f32 "
                "{%0,%1,%2,%3}, {%4,%5,%6,%7}, {%8,%9}, {%0,%1,%2,%3};"
                : "+f"(acc[nt0 + 1][0]), "+f"(acc[nt0 + 1][1]),
                  "+f"(acc[nt0 + 1][2]), "+f"(acc[nt0 + 1][3])
                : "r"(ua0), "r"(ua1), "r"(ua2), "r"(ua3),
                  "r"(b2r), "r"(b3r));
        }
    }
    __syncthreads();   // done with sW/sA; reuse smem as fp32 h staging

    #pragma unroll
    for (int half = 0; half < 2; half++) {
        if ((wid >> 2) == half) {
            int lr = (wid & 3) * 16;
            #pragma unroll
            for (int nt = 0; nt < 16; nt++) {
                int c = nt * 8 + 2 * tig;
                float b0 = sBias[c], b1 = sBias[c + 1];
                float2 q0 = make_float2(acc[nt][0] + b0, acc[nt][1] + b1);
                float2 q1 = make_float2(acc[nt][2] + b0, acc[nt][3] + b1);
                *reinterpret_cast<float2*>(&sH[(lr + g) * LDPF + c]) = q0;
                *reinterpret_cast<float2*>(&sH[(lr + g + 8) * LDPF + c]) = q1;
            }
        }
        __syncthreads();
        int base = half * 64;
        int valid = N - row0 - base;
        if (valid > 64) valid = 64;
        {
            int col = tid & 127;
            int rbeg = (tid >> 7) * 32;
            int rend = rbeg + 32;
            if (rend > valid) rend = valid;
            float s = 0.f, s2 = 0.f;
            for (int r = rbeg; r < rend; r++) {
                float v = sH[r * LDPF + col];
                s += v;
                s2 += v * v;
            }
            if (rbeg < valid) {
                atomicAdd(&g_colsum[col], s);
                atomicAdd(&g_colsumsq[col], s2);
            }
        }
        #pragma unroll
        for (int it = 0; it < 8; it++) {
            int idx = it * 256 + tid;
            int r = idx >> 5;
            int kc = idx & 31;
            int gr = row0 + base + r;
            if (gr < N) {
                float4 v = *reinterpret_cast<float4*>(&sH[r * LDPF + kc * 4]);
                reinterpret_cast<float4*>(h)[(size_t)gr * 32 + kc] = v;
            }
        }
        if (half == 0) __syncthreads();
    }
}

// ---------------- K4: grid-stride finalize with inline BN fold -------------
__global__ void __launch_bounds__(256)
k_final(const float* __restrict__ feat, const float* __restrict__ gamma,
        const float* __restrict__ beta, float* __restrict__ out,
        float invN, int nf4) {
    __shared__ float sScale[DDIM];
    __shared__ float sShift[DDIM];
    int tid = threadIdx.x;
    if (tid < DDIM) {
        float mean = g_colsum[tid] * invN;
        float var = g_colsumsq[tid] * invN - mean * mean;
        float rstd = rsqrtf(var + EPS);
        float sc = rstd * gamma[tid];
        sScale[tid] = sc;
        sShift[tid] = beta[tid] - mean * sc;
    }
    __syncthreads();
    int stride = gridDim.x * blockDim.x;
    for (int i = blockIdx.x * blockDim.x + tid; i < nf4; i += stride) {
        int c = (i & 31) << 2;
        float4 hv = reinterpret_cast<float4*>(out)[i];
        float4 fv = reinterpret_cast<const float4*>(feat)[i];
        float4 o;
        o.x = fmaxf(hv.x * sScale[c + 0] + sShift[c + 0], 0.f) + fv.x;
        o.y = fmaxf(hv.y * sScale[c + 1] + sShift[c + 1], 0.f) + fv.y;
        o.z = fmaxf(hv.z * sScale[c + 2] + sShift[c + 2], 0.f) + fv.z;
        o.w = fmaxf(hv.w * sScale[c + 3] + sShift[c + 3], 0.f) + fv.w;
        reinterpret_cast<float4*>(out)[i] = o;
    }
}

// ---------------- launch ----------------
extern "C" void kernel_launch(void* const* d_in, const int* in_sizes, int n_in,
                              void* d_out, int out_size) {
    const float* feature = (const float*)d_in[0];
    const int*   src     = (const int*)d_in[1];
    const int*   dst     = (const int*)d_in[2];
    const float* W       = (const float*)d_in[3];
    const float* b       = (const float*)d_in[4];
    const float* gamma   = (const float*)d_in[5];
    const float* beta    = (const float*)d_in[6];
    float* out = (float*)d_out;

    int N = in_sizes[0] / DDIM;   // 100000
    int E = in_sizes[1];          // 1000000
    int nf4 = N * (DDIM / 4);

    k_init<<<592, 256>>>(feature, N, nf4);
    k_insert<<<(E + 255) / 256, 256>>>(src, dst, E);

    int gw_blocks = ((N * 32) + 255) / 256;
    k_gather<<<gw_blocks, 256>>>(N);

    size_t smem = (size_t)(2 * 128 * LDPH) * sizeof(__half);   // 69632 B
    cudaFuncSetAttribute(k_gemm_mma,
                         cudaFuncAttributeMaxDynamicSharedMemorySize,
                         (int)smem);
    int gblocks = (N + 127) / 128;
    k_gemm_mma<<<gblocks, 256, smem>>>(W, b, out, N);

    k_final<<<1184, 256>>>(feature, gamma, beta, out, 1.0f / (float)N, nf4);
}

// round 12
// speedup vs baseline: 1.0948x; 1.0488x over previous
#include <cuda_runtime.h>
#include <cuda_fp16.h>
#include <cstdint>

#define DDIM 128
#define NMAX 100000
#define EMAX 1000000
#define EPS 1e-5f
#define SLOTS 64

// ---------------- scratch (device globals; no runtime allocation) ----------
__device__ __align__(256) __half g_agg16[(size_t)NMAX * DDIM];
__device__ __align__(256) __half g_feat16[(size_t)NMAX * DDIM];
__device__ __align__(256) __half g_w16[DDIM * DDIM];
__device__ __align__(256) int g_cnt[NMAX];
__device__ __align__(256) int g_ell[(size_t)NMAX * SLOTS];
__device__ __align__(16) float g_colsum[DDIM];
__device__ __align__(16) float g_colsumsq[DDIM];

// ------- K0: zero counters/stats + feature -> fp16 + W -> fp16 -------------
__global__ void __launch_bounds__(256) k_init(const float* __restrict__ feat,
                                              const float* __restrict__ W,
                                              int N, int nf4) {
    int stride = gridDim.x * blockDim.x;
    int tid0 = blockIdx.x * blockDim.x + threadIdx.x;
    for (int j = tid0; j < N; j += stride) g_cnt[j] = 0;
    if (tid0 < DDIM) { g_colsum[tid0] = 0.f; g_colsumsq[tid0] = 0.f; }
    if (tid0 < DDIM * DDIM / 4) {
        float4 v = reinterpret_cast<const float4*>(W)[tid0];
        __half2 h0 = __floats2half2_rn(v.x, v.y);
        __half2 h1 = __floats2half2_rn(v.z, v.w);
        uint2 u;
        u.x = *reinterpret_cast<uint32_t*>(&h0);
        u.y = *reinterpret_cast<uint32_t*>(&h1);
        reinterpret_cast<uint2*>(g_w16)[tid0] = u;
    }
    for (int i = tid0; i < nf4; i += stride) {
        float4 v = reinterpret_cast<const float4*>(feat)[i];
        __half2 h0 = __floats2half2_rn(v.x, v.y);
        __half2 h1 = __floats2half2_rn(v.z, v.w);
        uint2 u;
        u.x = *reinterpret_cast<uint32_t*>(&h0);
        u.y = *reinterpret_cast<uint32_t*>(&h1);
        reinterpret_cast<uint2*>(g_feat16)[i] = u;
    }
}

// ---------------- K1: ELL insert ----------------
__global__ void k_insert(const int* __restrict__ src,
                         const int* __restrict__ dst, int E) {
    int i = blockIdx.x * blockDim.x + threadIdx.x;
    if (i >= E) return;
    int d = dst[i];
    int pos = atomicAdd(&g_cnt[d], 1);
    if (pos < SLOTS) g_ell[d * SLOTS + pos] = src[i];
}

// ---------------- K2: gather-mean per node (1 warp / node), fp16 in/out ----
__global__ void __launch_bounds__(256) k_gather(int N) {
    uint32_t node = (blockIdx.x * blockDim.x + threadIdx.x) >> 5;
    uint32_t lane = threadIdx.x & 31;
    if (node >= (uint32_t)N) return;
    int cnt = g_cnt[node];
    int m = cnt < SLOTS ? cnt : SLOTS;
    const int* slots = g_ell + node * SLOTS;
    const uint2* f2p = reinterpret_cast<const uint2*>(g_feat16);
    float4 acc = make_float4(0.f, 0.f, 0.f, 0.f);
    int e = 0;
    for (; e + 4 <= m; e += 4) {
        uint32_t s0 = (uint32_t)slots[e] * 32u + lane;
        uint32_t s1 = (uint32_t)slots[e + 1] * 32u + lane;
        uint32_t s2 = (uint32_t)slots[e + 2] * 32u + lane;
        uint32_t s3 = (uint32_t)slots[e + 3] * 32u + lane;
        uint2 u0 = f2p[s0];
        uint2 u1 = f2p[s1];
        uint2 u2 = f2p[s2];
        uint2 u3 = f2p[s3];
        __half2 p0 = __hadd2(*reinterpret_cast<__half2*>(&u0.x),
                             *reinterpret_cast<__half2*>(&u1.x));
        __half2 p1 = __hadd2(*reinterpret_cast<__half2*>(&u0.y),
                             *reinterpret_cast<__half2*>(&u1.y));
        __half2 q0 = __hadd2(*reinterpret_cast<__half2*>(&u2.x),
                             *reinterpret_cast<__half2*>(&u3.x));
        __half2 q1 = __hadd2(*reinterpret_cast<__half2*>(&u2.y),
                             *reinterpret_cast<__half2*>(&u3.y));
        float2 f0 = __half22float2(p0);
        float2 f1 = __half22float2(p1);
        float2 e0 = __half22float2(q0);
        float2 e1 = __half22float2(q1);
        acc.x += f0.x + e0.x;
        acc.y += f0.y + e0.y;
        acc.z += f1.x + e1.x;
        acc.w += f1.y + e1.y;
    }
    if (e + 2 <= m) {
        uint32_t s0 = (uint32_t)slots[e] * 32u + lane;
        uint32_t s1 = (uint32_t)slots[e + 1] * 32u + lane;
        uint2 u0 = f2p[s0];
        uint2 u1 = f2p[s1];
        __half2 p0 = __hadd2(*reinterpret_cast<__half2*>(&u0.x),
                             *reinterpret_cast<__half2*>(&u1.x));
        __half2 p1 = __hadd2(*reinterpret_cast<__half2*>(&u0.y),
                             *reinterpret_cast<__half2*>(&u1.y));
        float2 f0 = __half22float2(p0);
        float2 f1 = __half22float2(p1);
        acc.x += f0.x; acc.y += f0.y; acc.z += f1.x; acc.w += f1.y;
        e += 2;
    }
    if (e < m) {
        uint32_t s0 = (uint32_t)slots[e] * 32u + lane;
        uint2 u0 = f2p[s0];
        float2 f0 = __half22float2(*reinterpret_cast<__half2*>(&u0.x));
        float2 f1 = __half22float2(*reinterpret_cast<__half2*>(&u0.y));
        acc.x += f0.x; acc.y += f0.y; acc.z += f1.x; acc.w += f1.y;
    }
    float inv = 1.0f / fmaxf((float)cnt, 1.0f);
    __half2 o0 = __floats2half2_rn(acc.x * inv, acc.y * inv);
    __half2 o1 = __floats2half2_rn(acc.z * inv, acc.w * inv);
    uint2 ov;
    ov.x = *reinterpret_cast<uint32_t*>(&o0);
    ov.y = *reinterpret_cast<uint32_t*>(&o1);
    reinterpret_cast<uint2*>(g_agg16)[node * 32u + lane] = ov;
}

// ------- K3: fp16 mma GEMM, M=64 tile, 128 thr, 4 CTA/SM -------------------
#define LDPH 136
#define LDPF 132
__global__ void __launch_bounds__(128, 4)
k_gemm_mma(const float* __restrict__ b, float* __restrict__ h, int N) {
    extern __shared__ __half smemh[];
    __half* sW = smemh;                  // [128][136] = 34816 B
    __half* sA = smemh + 128 * LDPH;     // [64][136]  = 17408 B
    float* sH = reinterpret_cast<float*>(smemh);   // epilogue: 64*132*4 B
    __shared__ float sBias[DDIM];

    int tid = threadIdx.x;
    int wid = tid >> 5;
    int lane = tid & 31;
    int g = lane >> 2;
    int tig = lane & 3;
    int row0 = blockIdx.x * 64;

    sBias[tid] = b[tid];

    // stage A (64 rows, fp16 uint4 coalesced: 1024 uint4 / 128 thr = 8)
    {
        const uint4* a4 = reinterpret_cast<const uint4*>(g_agg16);
        #pragma unroll
        for (int it = 0; it < 8; it++) {
            int idx = it * 128 + tid;
            int r = idx >> 4;
            int c = idx & 15;
            int gr = row0 + r;
            uint4 v = (gr < N) ? a4[(size_t)gr * 16 + c]
                               : make_uint4(0u, 0u, 0u, 0u);
            *reinterpret_cast<uint4*>(&sA[r * LDPH + c * 8]) = v;
        }
    }
    // stage W (fp16 global, straight copy: 2048 uint4 / 128 thr = 16)
    {
        const uint4* w4 = reinterpret_cast<const uint4*>(g_w16);
        #pragma unroll
        for (int it = 0; it < 16; it++) {
            int idx = it * 128 + tid;
            int r = idx >> 4;
            int c = idx & 15;
            uint4 v = w4[r * 16 + c];
            *reinterpret_cast<uint4*>(&sW[r * LDPH + c * 8]) = v;
        }
    }
    __syncthreads();

    int wr = wid * 16;
    float acc[16][4];
    #pragma unroll
    for (int nt = 0; nt < 16; nt++)
        #pragma unroll
        for (int c = 0; c < 4; c++) acc[nt][c] = 0.f;

    uint32_t sW_u32 = (uint32_t)__cvta_generic_to_shared(sW);
    uint32_t sA_u32 = (uint32_t)__cvta_generic_to_shared(sA);
    uint32_t b_lrow = ((lane >> 4) & 1) * 8 + (lane & 7);
    uint32_t b_khalf = ((lane >> 3) & 1) * 8;
    uint32_t b_laneoff = sW_u32 + 2u * (b_lrow * LDPH + b_khalf);
    uint32_t a_row = (uint32_t)wr + ((lane >> 3) & 1) * 8 + (lane & 7);
    uint32_t a_khalf = (lane >> 4) * 8;
    uint32_t a_laneoff = sA_u32 + 2u * (a_row * LDPH + a_khalf);

    #pragma unroll
    for (int ks = 0; ks < 8; ks++) {
        int k0 = ks * 16;
        uint32_t ua0, ua1, ua2, ua3;
        asm volatile(
            "ldmatrix.sync.aligned.m8n8.x4.shared.b16 {%0,%1,%2,%3}, [%4];"
            : "=r"(ua0), "=r"(ua1), "=r"(ua2), "=r"(ua3)
            : "r"(a_laneoff + 2u * (uint32_t)k0));
        #pragma unroll
        for (int ntp = 0; ntp < 8; ntp++) {
            uint32_t addr = b_laneoff + 2u * (ntp * 16 * LDPH + k0);
            uint32_t b0r, b1r, b2r, b3r;
            asm volatile(
                "ldmatrix.sync.aligned.m8n8.x4.shared.b16 {%0,%1,%2,%3}, [%4];"
                : "=r"(b0r), "=r"(b1r), "=r"(b2r), "=r"(b3r) : "r"(addr));
            int nt0 = ntp * 2;
            asm volatile(
                "mma.sync.aligned.m16n8k16.row.col.f32.f16.f16.f32 "
                "{%0,%1,%2,%3}, {%4,%5,%6,%7}, {%8,%9}, {%0,%1,%2,%3};"
                : "+f"(acc[nt0][0]), "+f"(acc[nt0][1]),
                  "+f"(acc[nt0][2]), "+f"(acc[nt0][3])
                : "r"(ua0), "r"(ua1), "r"(ua2), "r"(ua3),
                  "r"(b0r), "r"(b1r));
            asm volatile(
                "mma.sync.aligned.m16n8k16.row.col.f32.f16.f16.f32 "
                "{%0,%1,%2,%3}, {%4,%5,%6,%7}, {%8,%9}, {%0,%1,%2,%3};"
                : "+f"(acc[nt0 + 1][0]), "+f"(acc[nt0 + 1][1]),
                  "+f"(acc[nt0 + 1][2]), "+f"(acc[nt0 + 1][3])
                : "r"(ua0), "r"(ua1), "r"(ua2), "r"(ua3),
                  "r"(b2r), "r"(b3r));
        }
    }
    __syncthreads();   // done with sW/sA; reuse smem as fp32 h staging

    // epilogue: single 64-row window
    {
        #pragma unroll
        for (int nt = 0; nt < 16; nt++) {
            int c = nt * 8 + 2 * tig;
            float b0 = sBias[c], b1 = sBias[c + 1];
            float2 q0 = make_float2(acc[nt][0] + b0, acc[nt][1] + b1);
            float2 q1 = make_float2(acc[nt][2] + b0, acc[nt][3] + b1);
            *reinterpret_cast<float2*>(&sH[(wr + g) * LDPF + c]) = q0;
            *reinterpret_cast<float2*>(&sH[(wr + g + 8) * LDPF + c]) = q1;
        }
    }
    __syncthreads();

    int valid = N - row0;
    if (valid > 64) valid = 64;
    {
        float s = 0.f, s2 = 0.f;
        for (int r = 0; r < valid; r++) {
            float v = sH[r * LDPF + tid];
            s += v;
            s2 += v * v;
        }
        atomicAdd(&g_colsum[tid], s);
        atomicAdd(&g_colsumsq[tid], s2);
    }

    #pragma unroll
    for (int it = 0; it < 16; it++) {
        int idx = it * 128 + tid;
        int r = idx >> 5;
        int kc = idx & 31;
        int gr = row0 + r;
        if (gr < N) {
            float4 v = *reinterpret_cast<float4*>(&sH[r * LDPF + kc * 4]);
            reinterpret_cast<float4*>(h)[(size_t)gr * 32 + kc] = v;
        }
    }
}

// ---------------- K4: grid-stride finalize with inline BN fold -------------
__global__ void __launch_bounds__(256)
k_final(const float* __restrict__ feat, const float* __restrict__ gamma,
        const float* __restrict__ beta, float* __restrict__ out,
        float invN, int nf4) {
    __shared__ float sScale[DDIM];
    __shared__ float sShift[DDIM];
    int tid = threadIdx.x;
    if (tid < DDIM) {
        float mean = g_colsum[tid] * invN;
        float var = g_colsumsq[tid] * invN - mean * mean;
        float rstd = rsqrtf(var + EPS);
        float sc = rstd * gamma[tid];
        sScale[tid] = sc;
        sShift[tid] = beta[tid] - mean * sc;
    }
    __syncthreads();
    int stride = gridDim.x * blockDim.x;
    for (int i = blockIdx.x * blockDim.x + tid; i < nf4; i += stride) {
        int c = (i & 31) << 2;
        float4 hv = reinterpret_cast<float4*>(out)[i];
        float4 fv = reinterpret_cast<const float4*>(feat)[i];
        float4 o;
        o.x = fmaxf(hv.x * sScale[c + 0] + sShift[c + 0], 0.f) + fv.x;
        o.y = fmaxf(hv.y * sScale[c + 1] + sShift[c + 1], 0.f) + fv.y;
        o.z = fmaxf(hv.z * sScale[c + 2] + sShift[c + 2], 0.f) + fv.z;
        o.w = fmaxf(hv.w * sScale[c + 3] + sShift[c + 3], 0.f) + fv.w;
        reinterpret_cast<float4*>(out)[i] = o;
    }
}

// ---------------- launch ----------------
extern "C" void kernel_launch(void* const* d_in, const int* in_sizes, int n_in,
                              void* d_out, int out_size) {
    const float* feature = (const float*)d_in[0];
    const int*   src     = (const int*)d_in[1];
    const int*   dst     = (const int*)d_in[2];
    const float* W       = (const float*)d_in[3];
    const float* b       = (const float*)d_in[4];
    const float* gamma   = (const float*)d_in[5];
    const float* beta    = (const float*)d_in[6];
    float* out = (float*)d_out;

    int N = in_sizes[0] / DDIM;   // 100000
    int E = in_sizes[1];          // 1000000
    int nf4 = N * (DDIM / 4);

    k_init<<<592, 256>>>(feature, W, N, nf4);
    k_insert<<<(E + 255) / 256, 256>>>(src, dst, E);

    int gw_blocks = ((N * 32) + 255) / 256;
    k_gather<<<gw_blocks, 256>>>(N);

    size_t smem = (size_t)(128 * LDPH + 64 * LDPH) * sizeof(__half); // 52224 B
    size_t smemf = (size_t)(64 * LDPF) * sizeof(float);              // 33792 B
    if (smemf > smem) smem = smemf;
    cudaFuncSetAttribute(k_gemm_mma,
                         cudaFuncAttributeMaxDynamicSharedMemorySize,
                         (int)smem);
    int gblocks = (N + 63) / 64;
    k_gemm_mma<<<gblocks, 128, smem>>>(b, out, N);

    k_final<<<1184, 256>>>(feature, gamma, beta, out, 1.0f / (float)N, nf4);
}